// round 1
// baseline (speedup 1.0000x reference)
#include <cuda_runtime.h>
#include <math.h>

#define NTOK 4096
#define DIM  1024
#define HID  2048
#define NE   8

#define BM 64
#define BN 64
#define BK 32
#define ASTRIDE (BM + 1)

// Scratch (device globals — no allocations allowed)
__device__ int   g_counts[NE];
__device__ int   g_off[NE + 1];
__device__ int   g_tok[NE * NTOK];
__device__ float g_wt[NE * NTOK];
__device__ float g_h[(size_t)(2 * NTOK) * HID];   // 8192 x 2048 fp32 = 64 MB

// ---------------------------------------------------------------------------
// K0: zero output + routing counts (runs every call — graph replays)
// ---------------------------------------------------------------------------
__global__ void zero_kernel(float* __restrict__ out, int n4) {
    int idx = blockIdx.x * blockDim.x + threadIdx.x;
    if (idx < NE) g_counts[idx] = 0;
    float4 z = make_float4(0.f, 0.f, 0.f, 0.f);
    float4* o4 = (float4*)out;
    for (int i = idx; i < n4; i += gridDim.x * blockDim.x) o4[i] = z;
}

// ---------------------------------------------------------------------------
// K1: routing — one warp per token. 8 gate dots, top-2, softmax over the 2,
// atomic append (token, weight) to per-expert lists.
// ---------------------------------------------------------------------------
__global__ void route_kernel(const float* __restrict__ x,
                             const float* __restrict__ Wg) {
    int warp = (blockIdx.x * blockDim.x + threadIdx.x) >> 5;
    int lane = threadIdx.x & 31;
    if (warp >= NTOK) return;
    const float* xr = x + (size_t)warp * DIM;

    float sc[NE];
#pragma unroll
    for (int e = 0; e < NE; e++) sc[e] = 0.f;

    for (int i = lane; i < DIM; i += 32) {
        float xv = xr[i];
#pragma unroll
        for (int e = 0; e < NE; e++) sc[e] += xv * Wg[i * NE + e];
    }
#pragma unroll
    for (int o = 16; o > 0; o >>= 1) {
#pragma unroll
        for (int e = 0; e < NE; e++)
            sc[e] += __shfl_xor_sync(0xffffffffu, sc[e], o);
    }

    if (lane == 0) {
        // top-1 (strict > keeps lowest index on ties, like jax top_k)
        int i0 = 0; float s0 = sc[0];
#pragma unroll
        for (int e = 1; e < NE; e++) if (sc[e] > s0) { s0 = sc[e]; i0 = e; }
        int i1 = -1; float s1 = -INFINITY;
#pragma unroll
        for (int e = 0; e < NE; e++)
            if (e != i0 && sc[e] > s1) { s1 = sc[e]; i1 = e; }

        // softmax over {s0, s1}, s0 >= s1
        float e1  = expf(s1 - s0);
        float inv = 1.f / (1.f + e1);
        float w0  = inv;
        float w1  = e1 * inv;

        int p0 = atomicAdd(&g_counts[i0], 1);
        g_tok[i0 * NTOK + p0] = warp;
        g_wt [i0 * NTOK + p0] = w0;
        int p1 = atomicAdd(&g_counts[i1], 1);
        g_tok[i1 * NTOK + p1] = warp;
        g_wt [i1 * NTOK + p1] = w1;
    }
}

// ---------------------------------------------------------------------------
// K2: exclusive scan of 8 counts (trivial)
// ---------------------------------------------------------------------------
__global__ void scan_kernel() {
    int acc = 0;
#pragma unroll
    for (int e = 0; e < NE; e++) { g_off[e] = acc; acc += g_counts[e]; }
    g_off[NE] = acc;
}

// ---------------------------------------------------------------------------
// K3: FFN1 grouped GEMM — per expert: Xe[cnt,1024] @ {W1[e], W3[e]} [1024,2048]
//     fused SwiGLU epilogue -> g_h. A tile shared between both B matrices.
// ---------------------------------------------------------------------------
__global__ __launch_bounds__(256) void ffn1_kernel(
    const float* __restrict__ x,
    const float* __restrict__ W1,
    const float* __restrict__ W3)
{
    int e   = blockIdx.z;
    int cnt = g_counts[e];
    int m0  = blockIdx.y * BM;
    if (m0 >= cnt) return;
    int n0   = blockIdx.x * BN;
    int base = g_off[e];

    const float* W1e = W1 + (size_t)e * DIM * HID;
    const float* W3e = W3 + (size_t)e * DIM * HID;

    __shared__ float As [BK][ASTRIDE];
    __shared__ float B1s[BK][BN];
    __shared__ float B3s[BK][BN];

    int tid = threadIdx.x;
    int tm = (tid >> 4) << 2;   // 0..60
    int tn = (tid & 15) << 2;   // 0..60

    float acc1[4][4] = {};
    float acc3[4][4] = {};

    for (int kb = 0; kb < DIM; kb += BK) {
        // A tile: 64x32 gathered rows, stored transposed (pad -> conflict-free)
#pragma unroll
        for (int t = 0; t < 2; t++) {
            int vec = tid + t * 256;          // 512 float4 slots
            int row = vec >> 3;               // BK/4 = 8 vecs per row
            int col = (vec & 7) << 2;
            int mg  = m0 + row;
            float4 v = make_float4(0.f, 0.f, 0.f, 0.f);
            if (mg < cnt) {
                int tok = g_tok[e * NTOK + mg];
                v = *(const float4*)(x + (size_t)tok * DIM + kb + col);
            }
            As[col + 0][row] = v.x;
            As[col + 1][row] = v.y;
            As[col + 2][row] = v.z;
            As[col + 3][row] = v.w;
        }
        // B tiles: 32x64 each, coalesced float4
#pragma unroll
        for (int t = 0; t < 2; t++) {
            int vec = tid + t * 256;
            int kr  = vec >> 4;               // BN/4 = 16 vecs per row
            int nc  = (vec & 15) << 2;
            size_t goff = (size_t)(kb + kr) * HID + n0 + nc;
            *(float4*)&B1s[kr][nc] = *(const float4*)(W1e + goff);
            *(float4*)&B3s[kr][nc] = *(const float4*)(W3e + goff);
        }
        __syncthreads();

#pragma unroll
        for (int k = 0; k < BK; k++) {
            float a[4];
#pragma unroll
            for (int i = 0; i < 4; i++) a[i] = As[k][tm + i];
            float4 b1 = *(float4*)&B1s[k][tn];
            float4 b3 = *(float4*)&B3s[k][tn];
            float bb1[4] = {b1.x, b1.y, b1.z, b1.w};
            float bb3[4] = {b3.x, b3.y, b3.z, b3.w};
#pragma unroll
            for (int i = 0; i < 4; i++)
#pragma unroll
                for (int j = 0; j < 4; j++) {
                    acc1[i][j] += a[i] * bb1[j];
                    acc3[i][j] += a[i] * bb3[j];
                }
        }
        __syncthreads();
    }

    // SwiGLU epilogue: h = silu(a1) * a3
#pragma unroll
    for (int i = 0; i < 4; i++) {
        int mg = m0 + tm + i;
        if (mg < cnt) {
            float* hrow = g_h + (size_t)(base + mg) * HID + n0 + tn;
            float4 hv;
            float a;
            a = acc1[i][0]; hv.x = a / (1.f + __expf(-a)) * acc3[i][0];
            a = acc1[i][1]; hv.y = a / (1.f + __expf(-a)) * acc3[i][1];
            a = acc1[i][2]; hv.z = a / (1.f + __expf(-a)) * acc3[i][2];
            a = acc1[i][3]; hv.w = a / (1.f + __expf(-a)) * acc3[i][3];
            *(float4*)hrow = hv;
        }
    }
}

// ---------------------------------------------------------------------------
// K4: FFN2 grouped GEMM — per expert: He[cnt,2048] @ W2[e][2048,1024],
//     epilogue: atomicAdd(out[tok], w * c)  (exactly 2 adds/element — commutative)
// ---------------------------------------------------------------------------
__global__ __launch_bounds__(256) void ffn2_kernel(
    const float* __restrict__ W2,
    float* __restrict__ out)
{
    int e   = blockIdx.z;
    int cnt = g_counts[e];
    int m0  = blockIdx.y * BM;
    if (m0 >= cnt) return;
    int n0   = blockIdx.x * BN;
    int base = g_off[e];

    const float* W2e = W2 + (size_t)e * HID * DIM;

    __shared__ float As[BK][ASTRIDE];
    __shared__ float Bs[BK][BN];

    int tid = threadIdx.x;
    int tm = (tid >> 4) << 2;
    int tn = (tid & 15) << 2;

    float acc[4][4] = {};

    for (int kb = 0; kb < HID; kb += BK) {
#pragma unroll
        for (int t = 0; t < 2; t++) {
            int vec = tid + t * 256;
            int row = vec >> 3;
            int col = (vec & 7) << 2;
            int mg  = m0 + row;
            float4 v = make_float4(0.f, 0.f, 0.f, 0.f);
            if (mg < cnt)
                v = *(const float4*)(g_h + (size_t)(base + mg) * HID + kb + col);
            As[col + 0][row] = v.x;
            As[col + 1][row] = v.y;
            As[col + 2][row] = v.z;
            As[col + 3][row] = v.w;
        }
#pragma unroll
        for (int t = 0; t < 2; t++) {
            int vec = tid + t * 256;
            int kr  = vec >> 4;
            int nc  = (vec & 15) << 2;
            *(float4*)&Bs[kr][nc] =
                *(const float4*)(W2e + (size_t)(kb + kr) * DIM + n0 + nc);
        }
        __syncthreads();

#pragma unroll
        for (int k = 0; k < BK; k++) {
            float a[4];
#pragma unroll
            for (int i = 0; i < 4; i++) a[i] = As[k][tm + i];
            float4 b = *(float4*)&Bs[k][tn];
            float bb[4] = {b.x, b.y, b.z, b.w};
#pragma unroll
            for (int i = 0; i < 4; i++)
#pragma unroll
                for (int j = 0; j < 4; j++)
                    acc[i][j] += a[i] * bb[j];
        }
        __syncthreads();
    }

#pragma unroll
    for (int i = 0; i < 4; i++) {
        int mg = m0 + tm + i;
        if (mg < cnt) {
            int   tok = g_tok[e * NTOK + mg];
            float w   = g_wt [e * NTOK + mg];
            float* orow = out + (size_t)tok * DIM + n0 + tn;
#pragma unroll
            for (int j = 0; j < 4; j++)
                atomicAdd(&orow[j], w * acc[i][j]);
        }
    }
}

// ---------------------------------------------------------------------------
// Launch — 5 kernels, graph-capturable, allocation-free
// Inputs (metadata order): x[2,2048,1024], Wg[1024,8], W1[8,1024,2048],
//                          W3[8,1024,2048], W2[8,2048,1024]; out fp32 [2,2048,1024]
// ---------------------------------------------------------------------------
extern "C" void kernel_launch(void* const* d_in, const int* in_sizes, int n_in,
                              void* d_out, int out_size) {
    const float* x  = (const float*)d_in[0];
    const float* Wg = (const float*)d_in[1];
    const float* W1 = (const float*)d_in[2];
    const float* W3 = (const float*)d_in[3];
    const float* W2 = (const float*)d_in[4];
    float* out = (float*)d_out;

    zero_kernel<<<1024, 256>>>(out, out_size / 4);
    route_kernel<<<NTOK / 8, 256>>>(x, Wg);      // 8 warps/block
    scan_kernel<<<1, 1>>>();

    dim3 g1(HID / BN, NTOK / BM, NE);            // 32 x 64 x 8
    ffn1_kernel<<<g1, 256>>>(x, W1, W3);

    dim3 g2(DIM / BN, NTOK / BM, NE);            // 16 x 64 x 8
    ffn2_kernel<<<g2, 256>>>(W2, out);
}

// round 3
// speedup vs baseline: 1.3436x; 1.3436x over previous
#include <cuda_runtime.h>
#include <cuda_bf16.h>
#include <math.h>
#include <stdint.h>

#define NTOK 4096
#define DIM  1024
#define HID  2048
#define NE   8
#define BK   32

// ---------------------------------------------------------------------------
// Helpers
// ---------------------------------------------------------------------------
__device__ __forceinline__ uint32_t smem_to_u32(const void* p) {
    uint32_t a;
    asm("{ .reg .u64 t; cvta.to.shared.u64 t, %1; cvt.u32.u64 %0, t; }"
        : "=r"(a) : "l"(p));
    return a;
}

#define SWZ(rel) ((rel) ^ (((rel) >> 3) & 0x70))

__device__ __forceinline__ void ldsm_x4(uint32_t addr, uint32_t* r) {
    asm volatile("ldmatrix.sync.aligned.m8n8.x4.shared.b16 {%0,%1,%2,%3}, [%4];"
        : "=r"(r[0]), "=r"(r[1]), "=r"(r[2]), "=r"(r[3]) : "r"(addr));
}
__device__ __forceinline__ void ldsm_x4_t(uint32_t addr, uint32_t* r) {
    asm volatile("ldmatrix.sync.aligned.m8n8.x4.trans.shared.b16 {%0,%1,%2,%3}, [%4];"
        : "=r"(r[0]), "=r"(r[1]), "=r"(r[2]), "=r"(r[3]) : "r"(addr));
}
__device__ __forceinline__ void mma_bf16(float* d, const uint32_t* a, const uint32_t* b) {
    asm volatile(
        "mma.sync.aligned.m16n8k16.row.col.f32.bf16.bf16.f32 "
        "{%0,%1,%2,%3}, {%4,%5,%6,%7}, {%8,%9}, {%0,%1,%2,%3};"
        : "+f"(d[0]), "+f"(d[1]), "+f"(d[2]), "+f"(d[3])
        : "r"(a[0]), "r"(a[1]), "r"(a[2]), "r"(a[3]), "r"(b[0]), "r"(b[1]));
}

// fp32 -> bf16 hi + lo
__device__ __forceinline__ void cvt_hl(float f, __nv_bfloat16& h, __nv_bfloat16& l) {
    h = __float2bfloat16_rn(f);
    l = __float2bfloat16_rn(f - __bfloat162float(h));
}
__device__ __forceinline__ uint32_t pack2(__nv_bfloat16 a, __nv_bfloat16 b) {
    __nv_bfloat162 t = __halves2bfloat162(a, b);
    uint32_t r; memcpy(&r, &t, 4); return r;
}
__device__ __forceinline__ void cvt4(float4 f, uint2& hv, uint2& lv) {
    __nv_bfloat16 h0,l0,h1,l1,h2,l2,h3,l3;
    cvt_hl(f.x, h0, l0); cvt_hl(f.y, h1, l1);
    cvt_hl(f.z, h2, l2); cvt_hl(f.w, h3, l3);
    hv.x = pack2(h0, h1); hv.y = pack2(h2, h3);
    lv.x = pack2(l0, l1); lv.y = pack2(l2, l3);
}

// ---------------------------------------------------------------------------
// Scratch (device globals)
// ---------------------------------------------------------------------------
__device__ int   g_counts[NE];
__device__ int   g_off[NE + 1];
__device__ int   g_tok[NE * NTOK];
__device__ float g_wt[NE * NTOK];
__device__ __nv_bfloat16 g_hh[(size_t)(2 * NTOK) * HID];   // hidden hi, 32 MB
__device__ __nv_bfloat16 g_hl[(size_t)(2 * NTOK) * HID];   // hidden lo, 32 MB

// ---------------------------------------------------------------------------
// K0: zero output + counts
// ---------------------------------------------------------------------------
__global__ void zero_kernel(float* __restrict__ out, int n4) {
    int idx = blockIdx.x * blockDim.x + threadIdx.x;
    if (idx < NE) g_counts[idx] = 0;
    float4 z = make_float4(0.f, 0.f, 0.f, 0.f);
    float4* o4 = (float4*)out;
    for (int i = idx; i < n4; i += gridDim.x * blockDim.x) o4[i] = z;
}

// ---------------------------------------------------------------------------
// K1: routing (one warp/token, top-2 + softmax, atomic append)
// ---------------------------------------------------------------------------
__global__ void route_kernel(const float* __restrict__ x,
                             const float* __restrict__ Wg) {
    int warp = (blockIdx.x * blockDim.x + threadIdx.x) >> 5;
    int lane = threadIdx.x & 31;
    if (warp >= NTOK) return;
    const float* xr = x + (size_t)warp * DIM;

    float sc[NE];
#pragma unroll
    for (int e = 0; e < NE; e++) sc[e] = 0.f;
    for (int i = lane; i < DIM; i += 32) {
        float xv = xr[i];
#pragma unroll
        for (int e = 0; e < NE; e++) sc[e] += xv * Wg[i * NE + e];
    }
#pragma unroll
    for (int o = 16; o > 0; o >>= 1)
#pragma unroll
        for (int e = 0; e < NE; e++)
            sc[e] += __shfl_xor_sync(0xffffffffu, sc[e], o);

    if (lane == 0) {
        int i0 = 0; float s0 = sc[0];
#pragma unroll
        for (int e = 1; e < NE; e++) if (sc[e] > s0) { s0 = sc[e]; i0 = e; }
        int i1 = -1; float s1 = -INFINITY;
#pragma unroll
        for (int e = 0; e < NE; e++)
            if (e != i0 && sc[e] > s1) { s1 = sc[e]; i1 = e; }
        float e1  = expf(s1 - s0);
        float inv = 1.f / (1.f + e1);
        int p0 = atomicAdd(&g_counts[i0], 1);
        g_tok[i0 * NTOK + p0] = warp;
        g_wt [i0 * NTOK + p0] = inv;
        int p1 = atomicAdd(&g_counts[i1], 1);
        g_tok[i1 * NTOK + p1] = warp;
        g_wt [i1 * NTOK + p1] = e1 * inv;
    }
}

__global__ void scan_kernel() {
    int acc = 0;
#pragma unroll
    for (int e = 0; e < NE; e++) { g_off[e] = acc; acc += g_counts[e]; }
    g_off[NE] = acc;
}

// ---------------------------------------------------------------------------
// K3: FFN1 — mma.sync bf16 3-pass. D1=X@W1e, D3=X@W3e, SwiGLU -> g_hh/g_hl.
// Block 128x64, BK=32, 8 warps (4M x 2N), warp tile 32x32.
// A smem row (128B): [hi k0..31 | lo k0..31].  B planes: [32k][64n] each.
// ---------------------------------------------------------------------------
__global__ __launch_bounds__(256) void ffn1_kernel(
    const float* __restrict__ x,
    const float* __restrict__ W1,
    const float* __restrict__ W3)
{
    __shared__ __align__(128) __nv_bfloat16 sA[128 * 64];       // 16 KB
    __shared__ __align__(128) __nv_bfloat16 sB1h[32 * 64];      // 4 KB x4
    __shared__ __align__(128) __nv_bfloat16 sB1l[32 * 64];
    __shared__ __align__(128) __nv_bfloat16 sB3h[32 * 64];
    __shared__ __align__(128) __nv_bfloat16 sB3l[32 * 64];
    __shared__ int s_tok[128];

    int e   = blockIdx.z;
    int cnt = g_counts[e];
    int m0  = blockIdx.y * 128;
    if (m0 >= cnt) return;
    int n0   = blockIdx.x * 64;
    int base = g_off[e];

    const float* W1e = W1 + (size_t)e * DIM * HID;
    const float* W3e = W3 + (size_t)e * DIM * HID;

    int tid = threadIdx.x, wid = tid >> 5, l = tid & 31;
    int mw = (wid >> 1) * 32, nw = (wid & 1) * 32;

    if (tid < 128) {
        int mg = m0 + tid;
        s_tok[tid] = (mg < cnt) ? g_tok[e * NTOK + mg] : -1;
    }
    __syncthreads();

    float acc1[2][4][4] = {};
    float acc3[2][4][4] = {};

    uint32_t aB  = smem_to_u32(sA);
    uint32_t b1h = smem_to_u32(sB1h), b1l = smem_to_u32(sB1l);
    uint32_t b3h = smem_to_u32(sB3h), b3l = smem_to_u32(sB3l);

    for (int it = 0; it < DIM / BK; it++) {
        int kb = it * BK;
        // ---- A: 128x32 fp32 gathered -> hi/lo packed ----
#pragma unroll
        for (int i = 0; i < 4; i++) {
            int v   = tid + i * 256;      // 1024 float4 slots
            int row = v >> 3;
            int col = (v & 7) << 2;
            int tok = s_tok[row];
            float4 f = make_float4(0.f, 0.f, 0.f, 0.f);
            if (tok >= 0)
                f = *(const float4*)(x + (size_t)tok * DIM + kb + col);
            uint2 hv, lv; cvt4(f, hv, lv);
            uint32_t r1 = row * 128 + col * 2;
            *(uint2*)((char*)sA + SWZ(r1)) = hv;
            uint32_t r2 = row * 128 + 64 + col * 2;
            *(uint2*)((char*)sA + SWZ(r2)) = lv;
        }
        // ---- B1, B3: 32x64 fp32 each ----
#pragma unroll
        for (int i = 0; i < 2; i++) {
            int v  = tid + i * 256;       // 512 float4 slots
            int kr = v >> 4;
            int nc = (v & 15) << 2;
            size_t g = (size_t)(kb + kr) * HID + n0 + nc;
            uint32_t rel = kr * 128 + nc * 2;
            uint32_t sw  = SWZ(rel);
            float4 f = *(const float4*)(W1e + g);
            uint2 hv, lv; cvt4(f, hv, lv);
            *(uint2*)((char*)sB1h + sw) = hv;
            *(uint2*)((char*)sB1l + sw) = lv;
            f = *(const float4*)(W3e + g);
            cvt4(f, hv, lv);
            *(uint2*)((char*)sB3h + sw) = hv;
            *(uint2*)((char*)sB3l + sw) = lv;
        }
        __syncthreads();

#pragma unroll
        for (int ks = 0; ks < 2; ks++) {
            uint32_t ah[2][4], al[2][4];
#pragma unroll
            for (int mt = 0; mt < 2; mt++) {
                int row  = mw + mt * 16 + ((l >> 3) & 1) * 8 + (l & 7);
                int kbyt = (ks * 16 + (l >> 4) * 8) * 2;
                uint32_t r1 = row * 128 + kbyt;
                ldsm_x4(aB + SWZ(r1), ah[mt]);
                uint32_t r2 = row * 128 + 64 + kbyt;
                ldsm_x4(aB + SWZ(r2), al[mt]);
            }
            int krow = ks * 16 + ((l >> 3) & 1) * 8 + (l & 7);
            uint32_t rb0 = krow * 128 + (nw + (l >> 4) * 8) * 2;
            uint32_t rb1 = rb0 + 32;
            uint32_t s0 = SWZ(rb0), s1 = SWZ(rb1);

            {   // W1
                uint32_t bh[8], bl[8];
                ldsm_x4_t(b1h + s0, bh); ldsm_x4_t(b1h + s1, bh + 4);
                ldsm_x4_t(b1l + s0, bl); ldsm_x4_t(b1l + s1, bl + 4);
#pragma unroll
                for (int mt = 0; mt < 2; mt++)
#pragma unroll
                    for (int nj = 0; nj < 4; nj++) {
                        mma_bf16(acc1[mt][nj], ah[mt], &bh[nj * 2]);
                        mma_bf16(acc1[mt][nj], ah[mt], &bl[nj * 2]);
                        mma_bf16(acc1[mt][nj], al[mt], &bh[nj * 2]);
                    }
            }
            {   // W3
                uint32_t bh[8], bl[8];
                ldsm_x4_t(b3h + s0, bh); ldsm_x4_t(b3h + s1, bh + 4);
                ldsm_x4_t(b3l + s0, bl); ldsm_x4_t(b3l + s1, bl + 4);
#pragma unroll
                for (int mt = 0; mt < 2; mt++)
#pragma unroll
                    for (int nj = 0; nj < 4; nj++) {
                        mma_bf16(acc3[mt][nj], ah[mt], &bh[nj * 2]);
                        mma_bf16(acc3[mt][nj], ah[mt], &bl[nj * 2]);
                        mma_bf16(acc3[mt][nj], al[mt], &bh[nj * 2]);
                    }
            }
        }
        __syncthreads();
    }

    // ---- epilogue: SwiGLU -> g_hh/g_hl (bf16 hi/lo) ----
#pragma unroll
    for (int mt = 0; mt < 2; mt++) {
#pragma unroll
        for (int half = 0; half < 2; half++) {
            int row = m0 + mw + mt * 16 + (l >> 2) + half * 8;
            if (row < cnt) {
                size_t rb = (size_t)(base + row) * HID + n0 + nw;
#pragma unroll
                for (int nj = 0; nj < 4; nj++) {
                    float a0 = acc1[mt][nj][half * 2 + 0];
                    float a1 = acc1[mt][nj][half * 2 + 1];
                    float h0 = a0 / (1.f + __expf(-a0)) * acc3[mt][nj][half * 2 + 0];
                    float h1 = a1 / (1.f + __expf(-a1)) * acc3[mt][nj][half * 2 + 1];
                    int c = nj * 8 + (l & 3) * 2;
                    __nv_bfloat16 h0h, h0l, h1h, h1l;
                    cvt_hl(h0, h0h, h0l); cvt_hl(h1, h1h, h1l);
                    *(uint32_t*)(g_hh + rb + c) = pack2(h0h, h1h);
                    *(uint32_t*)(g_hl + rb + c) = pack2(h0l, h1l);
                }
            }
        }
    }
}

// ---------------------------------------------------------------------------
// K4: FFN2 — mma.sync bf16 3-pass. D = H@W2e, epilogue atomicAdd(out, w*c).
// ---------------------------------------------------------------------------
__global__ __launch_bounds__(256) void ffn2_kernel(
    const float* __restrict__ W2,
    float* __restrict__ out)
{
    __shared__ __align__(128) __nv_bfloat16 sA[128 * 64];   // 16 KB, hi|lo packed
    __shared__ __align__(128) __nv_bfloat16 sBh[32 * 64];   // 4 KB
    __shared__ __align__(128) __nv_bfloat16 sBl[32 * 64];

    int e   = blockIdx.z;
    int cnt = g_counts[e];
    int m0  = blockIdx.y * 128;
    if (m0 >= cnt) return;
    int n0   = blockIdx.x * 64;
    int base = g_off[e];

    const float* W2e = W2 + (size_t)e * HID * DIM;

    int tid = threadIdx.x, wid = tid >> 5, l = tid & 31;
    int mw = (wid >> 1) * 32, nw = (wid & 1) * 32;

    float acc[2][4][4] = {};

    uint32_t aB = smem_to_u32(sA);
    uint32_t bH = smem_to_u32(sBh), bL = smem_to_u32(sBl);

    for (int it = 0; it < HID / BK; it++) {
        int kb = it * BK;
        // ---- A: 128x32 bf16 hi/lo straight copies (16B each) ----
#pragma unroll
        for (int i = 0; i < 2; i++) {
            int v   = tid + i * 256;      // 512 slots (128 rows x 4 segs)
            int row = v >> 2;
            int seg = (v & 3) * 8;        // bf16 elements
            int mg  = m0 + row;
            uint4 hv = make_uint4(0, 0, 0, 0), lv = make_uint4(0, 0, 0, 0);
            if (mg < cnt) {
                size_t g = (size_t)(base + mg) * HID + kb + seg;
                hv = *(const uint4*)(g_hh + g);
                lv = *(const uint4*)(g_hl + g);
            }
            uint32_t r1 = row * 128 + seg * 2;
            *(uint4*)((char*)sA + SWZ(r1)) = hv;
            uint32_t r2 = row * 128 + 64 + seg * 2;
            *(uint4*)((char*)sA + SWZ(r2)) = lv;
        }
        // ---- B: 32x64 fp32 -> hi/lo ----
#pragma unroll
        for (int i = 0; i < 2; i++) {
            int v  = tid + i * 256;
            int kr = v >> 4;
            int nc = (v & 15) << 2;
            float4 f = *(const float4*)(W2e + (size_t)(kb + kr) * DIM + n0 + nc);
            uint2 hv, lv; cvt4(f, hv, lv);
            uint32_t rel = kr * 128 + nc * 2;
            uint32_t sw  = SWZ(rel);
            *(uint2*)((char*)sBh + sw) = hv;
            *(uint2*)((char*)sBl + sw) = lv;
        }
        __syncthreads();

#pragma unroll
        for (int ks = 0; ks < 2; ks++) {
            uint32_t ah[2][4], al[2][4];
#pragma unroll
            for (int mt = 0; mt < 2; mt++) {
                int row  = mw + mt * 16 + ((l >> 3) & 1) * 8 + (l & 7);
                int kbyt = (ks * 16 + (l >> 4) * 8) * 2;
                uint32_t r1 = row * 128 + kbyt;
                ldsm_x4(aB + SWZ(r1), ah[mt]);
                uint32_t r2 = row * 128 + 64 + kbyt;
                ldsm_x4(aB + SWZ(r2), al[mt]);
            }
            int krow = ks * 16 + ((l >> 3) & 1) * 8 + (l & 7);
            uint32_t rb0 = krow * 128 + (nw + (l >> 4) * 8) * 2;
            uint32_t rb1 = rb0 + 32;
            uint32_t s0 = SWZ(rb0), s1 = SWZ(rb1);

            uint32_t bh[8], bl[8];
            ldsm_x4_t(bH + s0, bh); ldsm_x4_t(bH + s1, bh + 4);
            ldsm_x4_t(bL + s0, bl); ldsm_x4_t(bL + s1, bl + 4);
#pragma unroll
            for (int mt = 0; mt < 2; mt++)
#pragma unroll
                for (int nj = 0; nj < 4; nj++) {
                    mma_bf16(acc[mt][nj], ah[mt], &bh[nj * 2]);
                    mma_bf16(acc[mt][nj], ah[mt], &bl[nj * 2]);
                    mma_bf16(acc[mt][nj], al[mt], &bh[nj * 2]);
                }
        }
        __syncthreads();
    }

    // ---- epilogue: out[tok] += w * acc ----
#pragma unroll
    for (int mt = 0; mt < 2; mt++) {
#pragma unroll
        for (int half = 0; half < 2; half++) {
            int row = m0 + mw + mt * 16 + (l >> 2) + half * 8;
            if (row < cnt) {
                int   tok = g_tok[e * NTOK + row];
                float w   = g_wt [e * NTOK + row];
                float* orow = out + (size_t)tok * DIM + n0 + nw;
#pragma unroll
                for (int nj = 0; nj < 4; nj++) {
                    int c = nj * 8 + (l & 3) * 2;
                    atomicAdd(&orow[c],     w * acc[mt][nj][half * 2 + 0]);
                    atomicAdd(&orow[c + 1], w * acc[mt][nj][half * 2 + 1]);
                }
            }
        }
    }
}

// ---------------------------------------------------------------------------
// Launch
// ---------------------------------------------------------------------------
extern "C" void kernel_launch(void* const* d_in, const int* in_sizes, int n_in,
                              void* d_out, int out_size) {
    const float* x  = (const float*)d_in[0];
    const float* Wg = (const float*)d_in[1];
    const float* W1 = (const float*)d_in[2];
    const float* W3 = (const float*)d_in[3];
    const float* W2 = (const float*)d_in[4];
    float* out = (float*)d_out;

    zero_kernel<<<1024, 256>>>(out, out_size / 4);
    route_kernel<<<NTOK / 8, 256>>>(x, Wg);
    scan_kernel<<<1, 1>>>();

    dim3 g1(HID / 64, NTOK / 128, NE);   // 32 x 32 x 8
    ffn1_kernel<<<g1, 256>>>(x, W1, W3);

    dim3 g2(DIM / 64, NTOK / 128, NE);   // 16 x 32 x 8
    ffn2_kernel<<<g2, 256>>>(W2, out);
}

// round 4
// speedup vs baseline: 2.4813x; 1.8468x over previous
#include <cuda_runtime.h>
#include <cuda_bf16.h>
#include <math.h>
#include <stdint.h>

#define NTOK 4096
#define DIM  1024
#define HID  2048
#define NE   8

// ---------------------------------------------------------------------------
// Helpers
// ---------------------------------------------------------------------------
__device__ __forceinline__ uint32_t smem_to_u32(const void* p) {
    uint32_t a;
    asm("{ .reg .u64 t; cvta.to.shared.u64 t, %1; cvt.u32.u64 %0, t; }"
        : "=r"(a) : "l"(p));
    return a;
}

#define SWZ(rel) ((rel) ^ (((rel) >> 3) & 0x70))

#define CP_ASYNC(dst, src, sz) \
    asm volatile("cp.async.cg.shared.global [%0], [%1], 16, %2;" \
        :: "r"(dst), "l"(src), "r"(sz))
#define CP_COMMIT() asm volatile("cp.async.commit_group;")
#define CP_WAIT(N)  asm volatile("cp.async.wait_group %0;" :: "n"(N))

__device__ __forceinline__ void ldsm_x4(uint32_t addr, uint32_t* r) {
    asm volatile("ldmatrix.sync.aligned.m8n8.x4.shared.b16 {%0,%1,%2,%3}, [%4];"
        : "=r"(r[0]), "=r"(r[1]), "=r"(r[2]), "=r"(r[3]) : "r"(addr));
}
__device__ __forceinline__ void ldsm_x4_t(uint32_t addr, uint32_t* r) {
    asm volatile("ldmatrix.sync.aligned.m8n8.x4.trans.shared.b16 {%0,%1,%2,%3}, [%4];"
        : "=r"(r[0]), "=r"(r[1]), "=r"(r[2]), "=r"(r[3]) : "r"(addr));
}
__device__ __forceinline__ void mma_bf16(float* d, const uint32_t* a, const uint32_t* b) {
    asm volatile(
        "mma.sync.aligned.m16n8k16.row.col.f32.bf16.bf16.f32 "
        "{%0,%1,%2,%3}, {%4,%5,%6,%7}, {%8,%9}, {%0,%1,%2,%3};"
        : "+f"(d[0]), "+f"(d[1]), "+f"(d[2]), "+f"(d[3])
        : "r"(a[0]), "r"(a[1]), "r"(a[2]), "r"(a[3]), "r"(b[0]), "r"(b[1]));
}

__device__ __forceinline__ void cvt_hl(float f, __nv_bfloat16& h, __nv_bfloat16& l) {
    h = __float2bfloat16_rn(f);
    l = __float2bfloat16_rn(f - __bfloat162float(h));
}
__device__ __forceinline__ uint32_t pack2(__nv_bfloat16 a, __nv_bfloat16 b) {
    __nv_bfloat162 t = __halves2bfloat162(a, b);
    uint32_t r; memcpy(&r, &t, 4); return r;
}
__device__ __forceinline__ void cvt4(float4 f, uint2& hv, uint2& lv) {
    __nv_bfloat16 h0,l0,h1,l1,h2,l2,h3,l3;
    cvt_hl(f.x, h0, l0); cvt_hl(f.y, h1, l1);
    cvt_hl(f.z, h2, l2); cvt_hl(f.w, h3, l3);
    hv.x = pack2(h0, h1); hv.y = pack2(h2, h3);
    lv.x = pack2(l0, l1); lv.y = pack2(l2, l3);
}

// ---------------------------------------------------------------------------
// Scratch (device globals)
// ---------------------------------------------------------------------------
__device__ int   g_counts[NE];
__device__ int   g_off[NE + 1];
__device__ int   g_tok[NE * NTOK];
__device__ float g_wt[NE * NTOK];
__device__ __nv_bfloat16 g_xh[(size_t)NTOK * DIM];
__device__ __nv_bfloat16 g_xl[(size_t)NTOK * DIM];
__device__ __nv_bfloat16 g_w1h[(size_t)NE * DIM * HID];
__device__ __nv_bfloat16 g_w1l[(size_t)NE * DIM * HID];
__device__ __nv_bfloat16 g_w3h[(size_t)NE * DIM * HID];
__device__ __nv_bfloat16 g_w3l[(size_t)NE * DIM * HID];
__device__ __nv_bfloat16 g_w2h[(size_t)NE * HID * DIM];
__device__ __nv_bfloat16 g_w2l[(size_t)NE * HID * DIM];
__device__ __nv_bfloat16 g_hh[(size_t)(2 * NTOK) * HID];
__device__ __nv_bfloat16 g_hl[(size_t)(2 * NTOK) * HID];

// ---------------------------------------------------------------------------
// K0: zero output + counts
// ---------------------------------------------------------------------------
__global__ void zero_kernel(float* __restrict__ out, int n4) {
    int idx = blockIdx.x * blockDim.x + threadIdx.x;
    if (idx < NE) g_counts[idx] = 0;
    float4 z = make_float4(0.f, 0.f, 0.f, 0.f);
    float4* o4 = (float4*)out;
    for (int i = idx; i < n4; i += gridDim.x * blockDim.x) o4[i] = z;
}

// ---------------------------------------------------------------------------
// K-cvt: fp32 -> bf16 hi/lo planes (which: 0=W1 1=W3 2=W2 3=x)
// ---------------------------------------------------------------------------
__global__ void cvt_kernel(const float4* __restrict__ src, int which, int n4) {
    __nv_bfloat16 *dh, *dl;
    if      (which == 0) { dh = g_w1h; dl = g_w1l; }
    else if (which == 1) { dh = g_w3h; dl = g_w3l; }
    else if (which == 2) { dh = g_w2h; dl = g_w2l; }
    else                 { dh = g_xh;  dl = g_xl;  }
    for (int i = blockIdx.x * blockDim.x + threadIdx.x; i < n4;
         i += gridDim.x * blockDim.x) {
        float4 f = src[i];
        uint2 hv, lv; cvt4(f, hv, lv);
        *(uint2*)(dh + (size_t)i * 4) = hv;
        *(uint2*)(dl + (size_t)i * 4) = lv;
    }
}

// ---------------------------------------------------------------------------
// K1: routing (one warp/token, top-2 + softmax, atomic append)
// ---------------------------------------------------------------------------
__global__ void route_kernel(const float* __restrict__ x,
                             const float* __restrict__ Wg) {
    int warp = (blockIdx.x * blockDim.x + threadIdx.x) >> 5;
    int lane = threadIdx.x & 31;
    if (warp >= NTOK) return;
    const float* xr = x + (size_t)warp * DIM;

    float sc[NE];
#pragma unroll
    for (int e = 0; e < NE; e++) sc[e] = 0.f;
    for (int i = lane; i < DIM; i += 32) {
        float xv = xr[i];
#pragma unroll
        for (int e = 0; e < NE; e++) sc[e] += xv * Wg[i * NE + e];
    }
#pragma unroll
    for (int o = 16; o > 0; o >>= 1)
#pragma unroll
        for (int e = 0; e < NE; e++)
            sc[e] += __shfl_xor_sync(0xffffffffu, sc[e], o);

    if (lane == 0) {
        int i0 = 0; float s0 = sc[0];
#pragma unroll
        for (int e = 1; e < NE; e++) if (sc[e] > s0) { s0 = sc[e]; i0 = e; }
        int i1 = -1; float s1 = -INFINITY;
#pragma unroll
        for (int e = 0; e < NE; e++)
            if (e != i0 && sc[e] > s1) { s1 = sc[e]; i1 = e; }
        float e1  = expf(s1 - s0);
        float inv = 1.f / (1.f + e1);
        int p0 = atomicAdd(&g_counts[i0], 1);
        g_tok[i0 * NTOK + p0] = warp;
        g_wt [i0 * NTOK + p0] = inv;
        int p1 = atomicAdd(&g_counts[i1], 1);
        g_tok[i1 * NTOK + p1] = warp;
        g_wt [i1 * NTOK + p1] = e1 * inv;
    }
}

__global__ void scan_kernel() {
    int acc = 0;
#pragma unroll
    for (int e = 0; e < NE; e++) { g_off[e] = acc; acc += g_counts[e]; }
    g_off[NE] = acc;
}

// ---------------------------------------------------------------------------
// K3: FFN1 — BM=128, BN=128 (both W1 and W3), BK=32, 512 thr, 2-stage cp.async.
// A smem row 128B: [hi k0..31 | lo k0..31].
// B smem: 4 planes (W1h,W1l,W3h,W3l) x [2 halves][32k x 64n] SW128.
// Per buffer: A 16KB + B 32KB = 48KB; x2 = 96KB dynamic.
// ---------------------------------------------------------------------------
__global__ __launch_bounds__(512, 1) void ffn1_kernel() {
    extern __shared__ char sm[];
    __shared__ int s_tok[128];

    int e   = blockIdx.z;
    int cnt = g_counts[e];
    int m0  = blockIdx.y * 128;
    if (m0 >= cnt) return;
    int n0   = blockIdx.x * 128;
    int base = g_off[e];

    int tid = threadIdx.x, wid = tid >> 5, l = tid & 31;
    int mw = (wid >> 2) * 32, nw = (wid & 3) * 32;
    int half = nw >> 6, nwl = nw & 63;

    if (tid < 128) {
        int mg = m0 + tid;
        s_tok[tid] = (mg < cnt) ? g_tok[e * NTOK + mg] : -1;
    }
    __syncthreads();

    uint32_t sbase = smem_to_u32(sm);
    size_t eoffW = (size_t)e * DIM * HID;

    auto load_tile = [&](int it, int b) {
        int kb = it * 32;
        uint32_t abase = sbase + b * 49152;
        uint32_t bbase = abase + 16384;
        // A: 1024 chunks of 16B (8 per row: 4 hi + 4 lo)
#pragma unroll
        for (int j = 0; j < 2; j++) {
            int c = tid + j * 512;
            int row = c >> 3, sub = c & 7;
            int pl = sub >> 2, cc = sub & 3;
            int tok = s_tok[row];
            const __nv_bfloat16* sp = pl ? g_xl : g_xh;
            const void* src = sp + ((size_t)(tok < 0 ? 0 : tok) * DIM + kb + cc * 8);
            uint32_t dst = abase + SWZ((uint32_t)(row * 128 + pl * 64 + cc * 16));
            int sz = (tok < 0) ? 0 : 16;
            CP_ASYNC(dst, src, sz);
        }
        // B: 2048 chunks over 4 planes
#pragma unroll
        for (int j = 0; j < 4; j++) {
            int c = tid + j * 512;
            int p = c >> 9, w = c & 511;
            int kr = w >> 4, n = (w & 15) * 8;
            const __nv_bfloat16* sp;
            if      (p == 0) sp = g_w1h;
            else if (p == 1) sp = g_w1l;
            else if (p == 2) sp = g_w3h;
            else             sp = g_w3l;
            const void* src = sp + (eoffW + (size_t)(kb + kr) * HID + n0 + n);
            uint32_t dst = bbase + p * 8192 + (n >> 6) * 4096
                         + SWZ((uint32_t)(kr * 128 + (n & 63) * 2));
            CP_ASYNC(dst, src, 16);
        }
    };

    float acc1[2][4][4] = {};
    float acc3[2][4][4] = {};

    load_tile(0, 0);
    CP_COMMIT();

    for (int it = 0; it < DIM / 32; it++) {
        int b = it & 1;
        if (it + 1 < DIM / 32) {
            load_tile(it + 1, b ^ 1);
            CP_COMMIT();
            CP_WAIT(1);
        } else {
            CP_WAIT(0);
        }
        __syncthreads();

        uint32_t aB = sbase + b * 49152;
        uint32_t bB = aB + 16384;
        uint32_t b1h = bB + 0 * 8192 + half * 4096;
        uint32_t b1l = bB + 1 * 8192 + half * 4096;
        uint32_t b3h = bB + 2 * 8192 + half * 4096;
        uint32_t b3l = bB + 3 * 8192 + half * 4096;

#pragma unroll
        for (int ks = 0; ks < 2; ks++) {
            uint32_t ah[2][4], al[2][4];
#pragma unroll
            for (int mt = 0; mt < 2; mt++) {
                int row  = mw + mt * 16 + ((l >> 3) & 1) * 8 + (l & 7);
                int kbyt = (ks * 16 + (l >> 4) * 8) * 2;
                ldsm_x4(aB + SWZ((uint32_t)(row * 128 + kbyt)), ah[mt]);
                ldsm_x4(aB + SWZ((uint32_t)(row * 128 + 64 + kbyt)), al[mt]);
            }
            int krow = ks * 16 + ((l >> 3) & 1) * 8 + (l & 7);
            uint32_t rb0 = krow * 128 + (nwl + (l >> 4) * 8) * 2;
            uint32_t rb1 = rb0 + 32;
            uint32_t s0 = SWZ(rb0), s1 = SWZ(rb1);

            {   // W1
                uint32_t bh[8], bl[8];
                ldsm_x4_t(b1h + s0, bh); ldsm_x4_t(b1h + s1, bh + 4);
                ldsm_x4_t(b1l + s0, bl); ldsm_x4_t(b1l + s1, bl + 4);
#pragma unroll
                for (int mt = 0; mt < 2; mt++)
#pragma unroll
                    for (int nj = 0; nj < 4; nj++) {
                        mma_bf16(acc1[mt][nj], ah[mt], &bh[nj * 2]);
                        mma_bf16(acc1[mt][nj], ah[mt], &bl[nj * 2]);
                        mma_bf16(acc1[mt][nj], al[mt], &bh[nj * 2]);
                    }
            }
            {   // W3
                uint32_t bh[8], bl[8];
                ldsm_x4_t(b3h + s0, bh); ldsm_x4_t(b3h + s1, bh + 4);
                ldsm_x4_t(b3l + s0, bl); ldsm_x4_t(b3l + s1, bl + 4);
#pragma unroll
                for (int mt = 0; mt < 2; mt++)
#pragma unroll
                    for (int nj = 0; nj < 4; nj++) {
                        mma_bf16(acc3[mt][nj], ah[mt], &bh[nj * 2]);
                        mma_bf16(acc3[mt][nj], ah[mt], &bl[nj * 2]);
                        mma_bf16(acc3[mt][nj], al[mt], &bh[nj * 2]);
                    }
            }
        }
        __syncthreads();
    }

    // ---- epilogue: SwiGLU -> g_hh/g_hl ----
#pragma unroll
    for (int mt = 0; mt < 2; mt++) {
#pragma unroll
        for (int hf = 0; hf < 2; hf++) {
            int row = m0 + mw + mt * 16 + (l >> 2) + hf * 8;
            if (row < cnt) {
                size_t rb = (size_t)(base + row) * HID + n0 + nw;
#pragma unroll
                for (int nj = 0; nj < 4; nj++) {
                    float a0 = acc1[mt][nj][hf * 2 + 0];
                    float a1 = acc1[mt][nj][hf * 2 + 1];
                    float h0 = a0 / (1.f + __expf(-a0)) * acc3[mt][nj][hf * 2 + 0];
                    float h1 = a1 / (1.f + __expf(-a1)) * acc3[mt][nj][hf * 2 + 1];
                    int c = nj * 8 + (l & 3) * 2;
                    __nv_bfloat16 h0h, h0l, h1h, h1l;
                    cvt_hl(h0, h0h, h0l); cvt_hl(h1, h1h, h1l);
                    *(uint32_t*)(g_hh + rb + c) = pack2(h0h, h1h);
                    *(uint32_t*)(g_hl + rb + c) = pack2(h0l, h1l);
                }
            }
        }
    }
}

// ---------------------------------------------------------------------------
// K4: FFN2 — BM=128, BN=128, BK=32, 512 thr, 2-stage cp.async.
// Per buffer: A 16KB + B 16KB = 32KB; x2 = 64KB dynamic.
// ---------------------------------------------------------------------------
__global__ __launch_bounds__(512, 1) void ffn2_kernel(float* __restrict__ out) {
    extern __shared__ char sm[];

    int e   = blockIdx.z;
    int cnt = g_counts[e];
    int m0  = blockIdx.y * 128;
    if (m0 >= cnt) return;
    int n0   = blockIdx.x * 128;
    int base = g_off[e];

    int tid = threadIdx.x, wid = tid >> 5, l = tid & 31;
    int mw = (wid >> 2) * 32, nw = (wid & 3) * 32;
    int half = nw >> 6, nwl = nw & 63;

    uint32_t sbase = smem_to_u32(sm);
    size_t eoffW = (size_t)e * HID * DIM;

    auto load_tile = [&](int it, int b) {
        int kb = it * 32;
        uint32_t abase = sbase + b * 32768;
        uint32_t bbase = abase + 16384;
        // A: 1024 chunks from g_hh/g_hl
#pragma unroll
        for (int j = 0; j < 2; j++) {
            int c = tid + j * 512;
            int row = c >> 3, sub = c & 7;
            int pl = sub >> 2, cc = sub & 3;
            int mg = m0 + row;
            bool v = mg < cnt;
            const __nv_bfloat16* sp = pl ? g_hl : g_hh;
            const void* src = sp + ((size_t)(v ? base + mg : 0) * HID + kb + cc * 8);
            uint32_t dst = abase + SWZ((uint32_t)(row * 128 + pl * 64 + cc * 16));
            int sz = v ? 16 : 0;
            CP_ASYNC(dst, src, sz);
        }
        // B: 1024 chunks over 2 planes (W2h, W2l)
#pragma unroll
        for (int j = 0; j < 2; j++) {
            int c = tid + j * 512;
            int p = c >> 9, w = c & 511;
            int kr = w >> 4, n = (w & 15) * 8;
            const __nv_bfloat16* sp = p ? g_w2l : g_w2h;
            const void* src = sp + (eoffW + (size_t)(kb + kr) * DIM + n0 + n);
            uint32_t dst = bbase + p * 8192 + (n >> 6) * 4096
                         + SWZ((uint32_t)(kr * 128 + (n & 63) * 2));
            CP_ASYNC(dst, src, 16);
        }
    };

    float acc[2][4][4] = {};

    load_tile(0, 0);
    CP_COMMIT();

    for (int it = 0; it < HID / 32; it++) {
        int b = it & 1;
        if (it + 1 < HID / 32) {
            load_tile(it + 1, b ^ 1);
            CP_COMMIT();
            CP_WAIT(1);
        } else {
            CP_WAIT(0);
        }
        __syncthreads();

        uint32_t aB = sbase + b * 32768;
        uint32_t bB = aB + 16384;
        uint32_t bH = bB + 0 * 8192 + half * 4096;
        uint32_t bL = bB + 1 * 8192 + half * 4096;

#pragma unroll
        for (int ks = 0; ks < 2; ks++) {
            uint32_t ah[2][4], al[2][4];
#pragma unroll
            for (int mt = 0; mt < 2; mt++) {
                int row  = mw + mt * 16 + ((l >> 3) & 1) * 8 + (l & 7);
                int kbyt = (ks * 16 + (l >> 4) * 8) * 2;
                ldsm_x4(aB + SWZ((uint32_t)(row * 128 + kbyt)), ah[mt]);
                ldsm_x4(aB + SWZ((uint32_t)(row * 128 + 64 + kbyt)), al[mt]);
            }
            int krow = ks * 16 + ((l >> 3) & 1) * 8 + (l & 7);
            uint32_t rb0 = krow * 128 + (nwl + (l >> 4) * 8) * 2;
            uint32_t rb1 = rb0 + 32;
            uint32_t s0 = SWZ(rb0), s1 = SWZ(rb1);

            uint32_t bh[8], bl[8];
            ldsm_x4_t(bH + s0, bh); ldsm_x4_t(bH + s1, bh + 4);
            ldsm_x4_t(bL + s0, bl); ldsm_x4_t(bL + s1, bl + 4);
#pragma unroll
            for (int mt = 0; mt < 2; mt++)
#pragma unroll
                for (int nj = 0; nj < 4; nj++) {
                    mma_bf16(acc[mt][nj], ah[mt], &bh[nj * 2]);
                    mma_bf16(acc[mt][nj], ah[mt], &bl[nj * 2]);
                    mma_bf16(acc[mt][nj], al[mt], &bh[nj * 2]);
                }
        }
        __syncthreads();
    }

    // ---- epilogue: out[tok] += w * acc ----
#pragma unroll
    for (int mt = 0; mt < 2; mt++) {
#pragma unroll
        for (int hf = 0; hf < 2; hf++) {
            int row = m0 + mw + mt * 16 + (l >> 2) + hf * 8;
            if (row < cnt) {
                int   tok = g_tok[e * NTOK + row];
                float w   = g_wt [e * NTOK + row];
                float* orow = out + (size_t)tok * DIM + n0 + nw;
#pragma unroll
                for (int nj = 0; nj < 4; nj++) {
                    int c = nj * 8 + (l & 3) * 2;
                    atomicAdd(&orow[c],     w * acc[mt][nj][hf * 2 + 0]);
                    atomicAdd(&orow[c + 1], w * acc[mt][nj][hf * 2 + 1]);
                }
            }
        }
    }
}

// ---------------------------------------------------------------------------
// Launch
// ---------------------------------------------------------------------------
extern "C" void kernel_launch(void* const* d_in, const int* in_sizes, int n_in,
                              void* d_out, int out_size) {
    const float* x  = (const float*)d_in[0];
    const float* Wg = (const float*)d_in[1];
    const float* W1 = (const float*)d_in[2];
    const float* W3 = (const float*)d_in[3];
    const float* W2 = (const float*)d_in[4];
    float* out = (float*)d_out;

    cudaFuncSetAttribute(ffn1_kernel,
        cudaFuncAttributeMaxDynamicSharedMemorySize, 98304);
    cudaFuncSetAttribute(ffn2_kernel,
        cudaFuncAttributeMaxDynamicSharedMemorySize, 65536);

    zero_kernel<<<1024, 256>>>(out, out_size / 4);

    int wn4 = NE * DIM * HID / 4;
    cvt_kernel<<<4096, 256>>>((const float4*)W1, 0, wn4);
    cvt_kernel<<<4096, 256>>>((const float4*)W3, 1, wn4);
    cvt_kernel<<<4096, 256>>>((const float4*)W2, 2, wn4);
    cvt_kernel<<<2048, 256>>>((const float4*)x,  3, NTOK * DIM / 4);

    route_kernel<<<NTOK / 8, 256>>>(x, Wg);
    scan_kernel<<<1, 1>>>();

    dim3 g1(HID / 128, NTOK / 128, NE);   // 16 x 32 x 8
    ffn1_kernel<<<g1, 512, 98304>>>();

    dim3 g2(DIM / 128, NTOK / 128, NE);   // 8 x 32 x 8
    ffn2_kernel<<<g2, 512, 65536>>>(out);
}